// round 1
// baseline (speedup 1.0000x reference)
#include <cuda_runtime.h>

// Handmade_conv2d: NCHW [32,128,64,64] (*) OIHW [256,128,3,3] -> [32,256,62,62]
// Direct conv, fp32 CUDA-core tiled baseline.
// Block tile: 64 oc x (2 oh x 32 ow). Thread tile: 4 oc x 4 ow.
// K loop over input channels in chunks of 8 through shared memory.

#define N_   32
#define C_   128
#define H_   64
#define W_   64
#define OC_  256
#define OH_  62
#define OW_  62
#define ICB  8

__global__ __launch_bounds__(256)
void conv2d_kernel(const float* __restrict__ in,
                   const float* __restrict__ wt,
                   float* __restrict__ out)
{
    // input tile: ICB channels x 4 rows x 34 cols (stride 34 -> row delta 2 mod 32, conflict-free)
    __shared__ float sIn[ICB][4][34];
    // weights: [ic][r*3+s][oc] so 16 spatial threads broadcast the same float4
    __shared__ float sW[ICB][9][64];

    const int ow0 = blockIdx.x * 32;          // 0 or 32
    const int oh0 = blockIdx.y * 2;           // 0..60
    const int nz  = blockIdx.z;               // n*4 + oc_block
    const int n   = nz >> 2;
    const int oc0 = (nz & 3) * 64;

    const int tid  = threadIdx.x;
    const int ocg  = tid >> 4;                // 0..15  -> oc group of 4
    const int sp   = tid & 15;                // 0..15  -> spatial group
    const int row  = sp >> 3;                 // 0..1   -> oh offset
    const int col4 = (sp & 7) * 4;            // 0..28  -> ow offset (x4)

    float acc[4][4];
    #pragma unroll
    for (int m = 0; m < 4; m++)
        #pragma unroll
        for (int j = 0; j < 4; j++)
            acc[m][j] = 0.0f;

    const float* inN = in + (size_t)n * C_ * H_ * W_;

    for (int icb = 0; icb < C_; icb += ICB) {
        // ---- load input tile: ICB x 4 x 34 = 1088 floats ----
        for (int idx = tid; idx < ICB * 4 * 34; idx += 256) {
            int ic  = idx / (4 * 34);
            int rem = idx - ic * (4 * 34);
            int r   = rem / 34;
            int c   = rem - r * 34;
            int ih  = oh0 + r;                 // always < 64
            int iw  = ow0 + c;                 // may exceed 63 for ow0=32
            float v = 0.0f;
            if (iw < W_) v = inN[((size_t)(icb + ic) * H_ + ih) * W_ + iw];
            sIn[ic][r][c] = v;
        }
        // ---- load weight tile: 64 oc x ICB x 9 = 4608 floats ----
        for (int idx = tid; idx < 64 * ICB * 9; idx += 256) {
            int oc  = idx / (ICB * 9);
            int rem = idx - oc * (ICB * 9);
            int ic  = rem / 9;
            int rs  = rem - ic * 9;
            sW[ic][rs][oc] = wt[((size_t)(oc0 + oc) * C_ + icb + ic) * 9 + rs];
        }
        __syncthreads();

        #pragma unroll
        for (int ic = 0; ic < ICB; ic++) {
            // 18 scalar input loads into registers (3 rows x 6 cols)
            float x[3][6];
            #pragma unroll
            for (int r = 0; r < 3; r++)
                #pragma unroll
                for (int t = 0; t < 6; t++)
                    x[r][t] = sIn[ic][row + r][col4 + t];

            #pragma unroll
            for (int r = 0; r < 3; r++) {
                #pragma unroll
                for (int s = 0; s < 3; s++) {
                    float4 w4 = *(const float4*)&sW[ic][r * 3 + s][ocg * 4];
                    #pragma unroll
                    for (int j = 0; j < 4; j++) {
                        float xv = x[r][s + j];
                        acc[0][j] += w4.x * xv;
                        acc[1][j] += w4.y * xv;
                        acc[2][j] += w4.z * xv;
                        acc[3][j] += w4.w * xv;
                    }
                }
            }
        }
        __syncthreads();
    }

    // ---- store 4 oc x 4 ow ----
    const int oh = oh0 + row;                  // always < 62
    #pragma unroll
    for (int m = 0; m < 4; m++) {
        int oc = oc0 + ocg * 4 + m;
        float* o = out + (((size_t)n * OC_ + oc) * OH_ + oh) * OW_;
        #pragma unroll
        for (int j = 0; j < 4; j++) {
            int ow = ow0 + col4 + j;
            if (ow < OW_) o[ow] = acc[m][j];
        }
    }
}

extern "C" void kernel_launch(void* const* d_in, const int* in_sizes, int n_in,
                              void* d_out, int out_size)
{
    const float* in = (const float*)d_in[0];   // [32,128,64,64]
    const float* wt = (const float*)d_in[1];   // [256,128,3,3]
    float* out      = (float*)d_out;           // [32,256,62,62]

    dim3 grid(2, 31, N_ * 4);                  // ow chunks, oh pairs, n*oc_blocks
    dim3 block(256);
    conv2d_kernel<<<grid, block>>>(in, wt, out);
}

// round 3
// speedup vs baseline: 4.5378x; 4.5378x over previous
#include <cuda_runtime.h>
#include <cuda_bf16.h>
#include <cstdint>

// Conv2d [32,128,64,64] x [256,128,3,3] -> [32,256,62,62], valid, stride 1.
// Implicit GEMM on mma.sync (HMMA) bf16 with 3-term split-bf16 for fp32 accuracy.
// CTA: D[sp=128 (2 oh x 64 ow), oc=128], K = 9 rs x 2 chunks of 64 channels.
// cp.async double-buffered smem, ldmatrix fragments, smem-transposed epilogue.

#define NB   32
#define CIN  128
#define HIN  64
#define WIN  64
#define OC   256
#define OHT  62
#define OWT  62
#define KC   64
#define NCHUNK 18

// device scratch
__device__ __align__(256) __nv_bfloat16 g_Whi[9 * OC * CIN];              // [rs][oc][c]
__device__ __align__(256) __nv_bfloat16 g_Wlo[9 * OC * CIN];
__device__ __align__(256) __nv_bfloat16 g_Xhi[(size_t)NB * HIN * WIN * CIN]; // [n][h][w][c]
__device__ __align__(256) __nv_bfloat16 g_Xlo[(size_t)NB * HIN * WIN * CIN];

__device__ __forceinline__ uint32_t smem_u32(const void* p) {
    uint32_t a;
    asm("{ .reg .u64 t; cvta.to.shared.u64 t, %1; cvt.u32.u64 %0, t; }" : "=r"(a) : "l"(p));
    return a;
}
#define SWZ(o) ((o) ^ (((o) >> 3) & 0x70))

__device__ __forceinline__ void cp16(uint32_t dst, const void* src, uint32_t srcsize) {
    asm volatile("cp.async.cg.shared.global [%0], [%1], 16, %2;"
                 :: "r"(dst), "l"(src), "r"(srcsize));
}
__device__ __forceinline__ void cp_commit() { asm volatile("cp.async.commit_group;"); }
__device__ __forceinline__ void cp_wait1() { asm volatile("cp.async.wait_group 1;"); }
__device__ __forceinline__ void cp_wait0() { asm volatile("cp.async.wait_group 0;"); }

__device__ __forceinline__ void ldsm4(uint32_t* r, uint32_t addr) {
    asm volatile("ldmatrix.sync.aligned.m8n8.x4.shared.b16 {%0,%1,%2,%3}, [%4];"
                 : "=r"(r[0]), "=r"(r[1]), "=r"(r[2]), "=r"(r[3]) : "r"(addr));
}
__device__ __forceinline__ void mma16816(float* d, const uint32_t* a, uint32_t b0, uint32_t b1) {
    asm volatile("mma.sync.aligned.m16n8k16.row.col.f32.bf16.bf16.f32 "
                 "{%0,%1,%2,%3}, {%4,%5,%6,%7}, {%8,%9}, {%0,%1,%2,%3};"
                 : "+f"(d[0]), "+f"(d[1]), "+f"(d[2]), "+f"(d[3])
                 : "r"(a[0]), "r"(a[1]), "r"(a[2]), "r"(a[3]), "r"(b0), "r"(b1));
}

// smem: 2 stages x (A 32KB + B 32KB) = 128KB; epilogue D_s aliases stage0.
#define STAGE_SZ  65536
#define A_OFF     0
#define B_OFF     32768
#define HL_SZ     16384
#define SMEM_TOTAL (2 * STAGE_SZ)

// ---------------- pre-pass kernels ----------------
__global__ void wcvt_kernel(const float* __restrict__ wt) {
    int idx = blockIdx.x * blockDim.x + threadIdx.x;
    if (idx >= 9 * OC * CIN) return;
    int c  = idx & 127;
    int oc = (idx >> 7) & 255;
    int rs = idx >> 15;
    float v = wt[((size_t)oc * CIN + c) * 9 + rs];
    __nv_bfloat16 hi = __float2bfloat16(v);
    __nv_bfloat16 lo = __float2bfloat16(v - __bfloat162float(hi));
    g_Whi[idx] = hi;
    g_Wlo[idx] = lo;
}

__global__ void xcvt_kernel(const float* __restrict__ in) {
    __shared__ float t[32][33];
    int nh = blockIdx.z;
    int n  = nh >> 6;
    int h  = nh & 63;
    int ct = blockIdx.y;
    int wt_ = blockIdx.x;
    int tx = threadIdx.x, ty = threadIdx.y;

    const float* src = in + (size_t)n * CIN * HIN * WIN + (size_t)h * WIN;
    #pragma unroll
    for (int k = 0; k < 4; k++) {
        int c = ct * 32 + ty + k * 8;
        int w = wt_ * 32 + tx;
        t[ty + k * 8][tx] = src[(size_t)c * (HIN * WIN) + w];
    }
    __syncthreads();
    #pragma unroll
    for (int k = 0; k < 4; k++) {
        int w = wt_ * 32 + ty + k * 8;
        int c = ct * 32 + tx;
        float v = t[tx][ty + k * 8];
        __nv_bfloat16 hi = __float2bfloat16(v);
        __nv_bfloat16 lo = __float2bfloat16(v - __bfloat162float(hi));
        size_t o = ((size_t)(n * 64 + h) * WIN + w) * CIN + c;
        g_Xhi[o] = hi;
        g_Xlo[o] = lo;
    }
}

// ---------------- main GEMM kernel ----------------
__global__ __launch_bounds__(256, 1)
void conv_mma_kernel(float* __restrict__ out) {
    extern __shared__ char smem[];
    const uint32_t sb = smem_u32(smem);
    const int tid  = threadIdx.x;
    const int wrp  = tid >> 5;
    const int lane = tid & 31;

    const int oh0 = blockIdx.x * 2;
    const int oc0 = blockIdx.y * 128;
    const int n   = blockIdx.z;

    const int wm = wrp & 1;            // M warp (0..1) -> m0 = wm*64
    const int wn = wrp >> 1;           // N warp (0..3) -> n0 = wn*32
    const int m0 = wm * 64;
    const int n0 = wn * 32;

    const __nv_bfloat16* Xh = g_Xhi + (size_t)n * HIN * WIN * CIN;
    const __nv_bfloat16* Xl = g_Xlo + (size_t)n * HIN * WIN * CIN;

    float acc[4][4][4];
    #pragma unroll
    for (int mt = 0; mt < 4; mt++)
        #pragma unroll
        for (int nt = 0; nt < 4; nt++)
            #pragma unroll
            for (int e = 0; e < 4; e++)
                acc[mt][nt][e] = 0.0f;

    // ---- chunk loader: chunk it = rs*2+cc into stage (it%2) ----
    auto load_chunk = [&](int it) {
        const int rs = it >> 1;           // 0..8 (it/2)
        const int cc = it & 1;
        const int r  = rs / 3, s = rs % 3;
        const uint32_t stage = (uint32_t)(it & 1) * STAGE_SZ;
        // A: 128 sp x 64c, hi+lo : 2048 cp.async of 16B
        #pragma unroll
        for (int i = 0; i < 8; i++) {
            int idx  = tid + i * 256;
            int hiLo = idx >> 10;
            int rem  = idx & 1023;
            int sp   = rem >> 3;
            int c8   = rem & 7;
            int row2 = sp >> 6, ow = sp & 63;
            int h = oh0 + row2 + r;
            int w = ow + s;
            uint32_t valid = (w < WIN) ? 16u : 0u;
            int wc = (w < WIN) ? w : (WIN - 1);
            const __nv_bfloat16* src =
                (hiLo ? Xl : Xh) + ((size_t)h * WIN + wc) * CIN + cc * KC + c8 * 8;
            uint32_t dst = sb + stage + A_OFF + hiLo * HL_SZ
                         + SWZ((uint32_t)sp * 128 + c8 * 16);
            cp16(dst, src, valid);
        }
        // B: 128 oc x 64c, hi+lo
        const __nv_bfloat16* WhB = g_Whi + (size_t)rs * OC * CIN + (size_t)oc0 * CIN + cc * KC;
        const __nv_bfloat16* WlB = g_Wlo + (size_t)rs * OC * CIN + (size_t)oc0 * CIN + cc * KC;
        #pragma unroll
        for (int i = 0; i < 8; i++) {
            int idx  = tid + i * 256;
            int hiLo = idx >> 10;
            int rem  = idx & 1023;
            int oc   = rem >> 3;
            int c8   = rem & 7;
            const __nv_bfloat16* src = (hiLo ? WlB : WhB) + (size_t)oc * CIN + c8 * 8;
            uint32_t dst = sb + stage + B_OFF + hiLo * HL_SZ
                         + SWZ((uint32_t)oc * 128 + c8 * 16);
            cp16(dst, src, 16u);
        }
        cp_commit();
    };

    load_chunk(0);

    const int lrow  = lane & 15;   // ldmatrix row within 16
    const int khalf = lane >> 4;   // 0/1 -> +8 k cols (16B)

    for (int it = 0; it < NCHUNK; it++) {
        if (it + 1 < NCHUNK) load_chunk(it + 1);
        if (it + 1 < NCHUNK) cp_wait1(); else cp_wait0();
        __syncthreads();

        const uint32_t stage = (uint32_t)(it & 1) * STAGE_SZ;
        const uint32_t aBase = sb + stage + A_OFF;
        const uint32_t bBase = sb + stage + B_OFF;

        #pragma unroll
        for (int ks = 0; ks < 4; ks++) {
            uint32_t Ah[4][4], Al[4][4];
            uint32_t Bh[2][4], Bl[2][4];
            #pragma unroll
            for (int mt = 0; mt < 4; mt++) {
                uint32_t off = SWZ((uint32_t)(m0 + mt * 16 + lrow) * 128
                                   + ks * 32 + khalf * 16);
                ldsm4(Ah[mt], aBase + off);
                ldsm4(Al[mt], aBase + HL_SZ + off);
            }
            #pragma unroll
            for (int nt2 = 0; nt2 < 2; nt2++) {
                uint32_t off = SWZ((uint32_t)(n0 + nt2 * 16 + lrow) * 128
                                   + ks * 32 + khalf * 16);
                ldsm4(Bh[nt2], bBase + off);
                ldsm4(Bl[nt2], bBase + HL_SZ + off);
            }
            // 3 terms: hi*hi, lo*hi, hi*lo
            #pragma unroll
            for (int t = 0; t < 3; t++) {
                #pragma unroll
                for (int mt = 0; mt < 4; mt++) {
                    const uint32_t* a = (t == 1) ? Al[mt] : Ah[mt];
                    #pragma unroll
                    for (int nt = 0; nt < 4; nt++) {
                        int nt2 = nt >> 1, sub = nt & 1;
                        const uint32_t* bsel = (t == 2) ? Bl[nt2] : Bh[nt2];
                        mma16816(acc[mt][nt], a, bsel[sub], bsel[sub + 2]);
                    }
                }
            }
        }
        __syncthreads();
    }

    // ---- epilogue: transpose via smem (D_s[oc][sp], 128x128 f32 at smem base) ----
    float* Ds = (float*)smem;
    const int g = lane >> 2;        // 0..7
    const int q = lane & 3;         // 0..3
    #pragma unroll
    for (int mt = 0; mt < 4; mt++) {
        #pragma unroll
        for (int nt = 0; nt < 4; nt++) {
            int row = m0 + mt * 16 + g;
            int col = n0 + nt * 8 + q * 2;
            Ds[(size_t)col * 128 + row]           = acc[mt][nt][0];
            Ds[(size_t)(col + 1) * 128 + row]     = acc[mt][nt][1];
            Ds[(size_t)col * 128 + row + 8]       = acc[mt][nt][2];
            Ds[(size_t)(col + 1) * 128 + row + 8] = acc[mt][nt][3];
        }
    }
    __syncthreads();

    const int ow = tid & 63;
    const int oq = tid >> 6;          // 0..3
    const bool valid = (ow < OWT);
    float* outBase = out + ((size_t)n * OC + oc0) * OHT * OWT;
    #pragma unroll 4
    for (int i = 0; i < 32; i++) {
        int oc = i * 4 + oq;
        #pragma unroll
        for (int row2 = 0; row2 < 2; row2++) {
            float v = Ds[(size_t)oc * 128 + row2 * 64 + ow];
            int oh = oh0 + row2;
            if (valid)
                outBase[(size_t)oc * (OHT * OWT) + (size_t)oh * OWT + ow] = v;
        }
    }
}

extern "C" void kernel_launch(void* const* d_in, const int* in_sizes, int n_in,
                              void* d_out, int out_size)
{
    const float* in = (const float*)d_in[0];   // [32,128,64,64]
    const float* wt = (const float*)d_in[1];   // [256,128,3,3]
    float* out      = (float*)d_out;           // [32,256,62,62]

    cudaFuncSetAttribute(conv_mma_kernel,
                         cudaFuncAttributeMaxDynamicSharedMemorySize, SMEM_TOTAL);

    wcvt_kernel<<<(9 * OC * CIN + 255) / 256, 256>>>(wt);
    xcvt_kernel<<<dim3(2, 4, NB * HIN), dim3(32, 8)>>>(in);
    conv_mma_kernel<<<dim3(31, 2, NB), 256, SMEM_TOTAL>>>(out);
}

// round 8
// speedup vs baseline: 6.7651x; 1.4908x over previous
#include <cuda_runtime.h>
#include <cuda_fp16.h>
#include <cstdint>

// Conv2d [32,128,64,64] x [256,128,3,3] -> [32,256,62,62], valid, stride 1.
// Implicit GEMM on mma.sync fp16 with 2-term split (x = hi+lo fp16, w = fp16).
// CTA: D[sp=128 (2 oh x 64 ow), oc=256], 512 thr, K = 9 rs x 2 chunks of 64 ch.

#define NB   32
#define CIN  128
#define HIN  64
#define WIN  64
#define OC   256
#define OHT  62
#define OWT  62
#define KC   64
#define NCHUNK 18

// device scratch
__device__ __align__(256) __half g_W[9 * OC * CIN];                  // [rs][oc][c] fp16
__device__ __align__(256) __half g_Xhi[(size_t)NB * HIN * WIN * CIN]; // [n][h][w][c]
__device__ __align__(256) __half g_Xlo[(size_t)NB * HIN * WIN * CIN];

__device__ __forceinline__ uint32_t smem_u32(const void* p) {
    uint32_t a;
    asm("{ .reg .u64 t; cvta.to.shared.u64 t, %1; cvt.u32.u64 %0, t; }" : "=r"(a) : "l"(p));
    return a;
}
#define SWZ(o) ((o) ^ (((o) >> 3) & 0x70))

__device__ __forceinline__ void cp16(uint32_t dst, const void* src, uint32_t srcsize) {
    asm volatile("cp.async.cg.shared.global [%0], [%1], 16, %2;"
                 :: "r"(dst), "l"(src), "r"(srcsize));
}
__device__ __forceinline__ void cp_commit() { asm volatile("cp.async.commit_group;"); }
__device__ __forceinline__ void cp_wait1() { asm volatile("cp.async.wait_group 1;"); }
__device__ __forceinline__ void cp_wait0() { asm volatile("cp.async.wait_group 0;"); }

__device__ __forceinline__ void ldsm4(uint32_t* r, uint32_t addr) {
    asm volatile("ldmatrix.sync.aligned.m8n8.x4.shared.b16 {%0,%1,%2,%3}, [%4];"
                 : "=r"(r[0]), "=r"(r[1]), "=r"(r[2]), "=r"(r[3]) : "r"(addr));
}
__device__ __forceinline__ void mma16816(float* d, const uint32_t* a, uint32_t b0, uint32_t b1) {
    asm volatile("mma.sync.aligned.m16n8k16.row.col.f32.f16.f16.f32 "
                 "{%0,%1,%2,%3}, {%4,%5,%6,%7}, {%8,%9}, {%0,%1,%2,%3};"
                 : "+f"(d[0]), "+f"(d[1]), "+f"(d[2]), "+f"(d[3])
                 : "r"(a[0]), "r"(a[1]), "r"(a[2]), "r"(a[3]), "r"(b0), "r"(b1));
}

// smem per stage: A hi 16KB + A lo 16KB + B 32KB = 64KB; 2 stages = 128KB.
#define STAGE_SZ  65536
#define A_OFF     0
#define A_LO      16384
#define B_OFF     32768
#define SMEM_TOTAL (2 * STAGE_SZ)
#define DS_STRIDE 132

// ---------------- pre-pass kernels ----------------
__global__ void wcvt_kernel(const float* __restrict__ wt) {
    int idx = blockIdx.x * blockDim.x + threadIdx.x;
    if (idx >= 9 * OC * CIN) return;
    int c  = idx & 127;
    int oc = (idx >> 7) & 255;
    int rs = idx >> 15;
    g_W[idx] = __float2half(wt[((size_t)oc * CIN + c) * 9 + rs]);
}

__global__ void xcvt_kernel(const float* __restrict__ in) {
    __shared__ float t[32][33];
    int nh = blockIdx.z;
    int n  = nh >> 6;
    int h  = nh & 63;
    int ct = blockIdx.y;
    int wt_ = blockIdx.x;
    int tx = threadIdx.x, ty = threadIdx.y;

    const float* src = in + (size_t)n * CIN * HIN * WIN + (size_t)h * WIN;
    #pragma unroll
    for (int k = 0; k < 4; k++) {
        int c = ct * 32 + ty + k * 8;
        int w = wt_ * 32 + tx;
        t[ty + k * 8][tx] = src[(size_t)c * (HIN * WIN) + w];
    }
    __syncthreads();
    #pragma unroll
    for (int k = 0; k < 4; k++) {
        int w = wt_ * 32 + ty + k * 8;
        int c = ct * 32 + tx;
        float v = t[tx][ty + k * 8];
        __half hi = __float2half(v);
        __half lo = __float2half(v - __half2float(hi));
        size_t o = ((size_t)(n * 64 + h) * WIN + w) * CIN + c;
        g_Xhi[o] = hi;
        g_Xlo[o] = lo;
    }
}

// ---------------- main GEMM kernel ----------------
__global__ __launch_bounds__(512, 1)
void conv_mma_kernel(float* __restrict__ out) {
    extern __shared__ char smem[];
    const uint32_t sb = smem_u32(smem);
    const int tid  = threadIdx.x;
    const int wrp  = tid >> 5;
    const int lane = tid & 31;

    const int oh0 = blockIdx.x * 2;
    const int n   = blockIdx.y;

    const int wm = wrp & 3;            // 4 M warps -> m0 = wm*32
    const int wn = wrp >> 2;           // 4 N warps -> n0 = wn*64
    const int m0 = wm * 32;
    const int n0 = wn * 64;

    const __half* Xh = g_Xhi + (size_t)n * HIN * WIN * CIN;
    const __half* Xl = g_Xlo + (size_t)n * HIN * WIN * CIN;

    float acc[2][8][4];
    #pragma unroll
    for (int mt = 0; mt < 2; mt++)
        #pragma unroll
        for (int nt = 0; nt < 8; nt++)
            #pragma unroll
            for (int e = 0; e < 4; e++)
                acc[mt][nt][e] = 0.0f;

    auto load_chunk = [&](int it) {
        const int rs = it >> 1;
        const int cc = it & 1;
        const int r  = rs / 3, s = rs % 3;
        const uint32_t stage = (uint32_t)(it & 1) * STAGE_SZ;
        // A: 128 sp x 64c hi+lo = 2048 x 16B
        #pragma unroll
        for (int i = 0; i < 4; i++) {
            int idx  = tid + i * 512;
            int hiLo = idx >> 10;
            int rem  = idx & 1023;
            int sp   = rem >> 3;
            int c8   = rem & 7;
            int row2 = sp >> 6, ow = sp & 63;
            int h = oh0 + row2 + r;
            int w = ow + s;
            uint32_t vbytes = (w < WIN) ? 16u : 0u;
            int wc = (w < WIN) ? w : (WIN - 1);
            const __half* src =
                (hiLo ? Xl : Xh) + ((size_t)h * WIN + wc) * CIN + cc * KC + c8 * 8;
            uint32_t dst = sb + stage + A_OFF + hiLo * 16384
                         + SWZ((uint32_t)sp * 128 + c8 * 16);
            cp16(dst, src, vbytes);
        }
        // B: 256 oc x 64c = 2048 x 16B
        const __half* Wp = g_W + (size_t)rs * OC * CIN + cc * KC;
        #pragma unroll
        for (int i = 0; i < 4; i++) {
            int idx = tid + i * 512;
            int oc  = idx >> 3;
            int c8  = idx & 7;
            const __half* src = Wp + (size_t)oc * CIN + c8 * 8;
            uint32_t dst = sb + stage + B_OFF + SWZ((uint32_t)oc * 128 + c8 * 16);
            cp16(dst, src, 16u);
        }
        cp_commit();
    };

    load_chunk(0);

    const int lrow  = lane & 15;
    const int khalf = lane >> 4;

    for (int it = 0; it < NCHUNK; it++) {
        if (it + 1 < NCHUNK) load_chunk(it + 1);
        if (it + 1 < NCHUNK) cp_wait1(); else cp_wait0();
        __syncthreads();

        const uint32_t stage = (uint32_t)(it & 1) * STAGE_SZ;
        const uint32_t aBase = sb + stage + A_OFF;
        const uint32_t bBase = sb + stage + B_OFF;

        #pragma unroll
        for (int ks = 0; ks < 4; ks++) {
            uint32_t Ah[2][4], Al[2][4];
            uint32_t Bf[4][4];
            #pragma unroll
            for (int mt = 0; mt < 2; mt++) {
                uint32_t off = SWZ((uint32_t)(m0 + mt * 16 + lrow) * 128
                                   + ks * 32 + khalf * 16);
                ldsm4(Ah[mt], aBase + off);
                ldsm4(Al[mt], aBase + 16384 + off);
            }
            #pragma unroll
            for (int nt2 = 0; nt2 < 4; nt2++) {
                uint32_t off = SWZ((uint32_t)(n0 + nt2 * 16 + lrow) * 128
                                   + ks * 32 + khalf * 16);
                ldsm4(Bf[nt2], bBase + off);
            }
            #pragma unroll
            for (int t = 0; t < 2; t++) {
                #pragma unroll
                for (int mt = 0; mt < 2; mt++) {
                    const uint32_t* a = t ? Al[mt] : Ah[mt];
                    #pragma unroll
                    for (int nt = 0; nt < 8; nt++) {
                        int nt2 = nt >> 1, sub = nt & 1;
                        mma16816(acc[mt][nt], a, Bf[nt2][sub], Bf[nt2][sub + 2]);
                    }
                }
            }
        }
        __syncthreads();
    }

    // ---- epilogue: two oc halves through smem transpose, conflict-free stride ----
    float* Ds = (float*)smem;
    const int g = lane >> 2;
    const int q = lane & 3;
    const int ow = tid & 63;
    const int oq = tid >> 6;              // 0..7
    const bool valid = (ow < OWT);
    float* outBase = out + (size_t)n * OC * OHT * OWT;

    #pragma unroll
    for (int half = 0; half < 2; half++) {
        __syncthreads();
        if ((n0 >> 7) == half) {
            int colBase = n0 & 127;
            #pragma unroll
            for (int mt = 0; mt < 2; mt++) {
                #pragma unroll
                for (int nt = 0; nt < 8; nt++) {
                    int row = m0 + mt * 16 + g;
                    int col = colBase + nt * 8 + q * 2;
                    Ds[(size_t)col * DS_STRIDE + row]           = acc[mt][nt][0];
                    Ds[(size_t)(col + 1) * DS_STRIDE + row]     = acc[mt][nt][1];
                    Ds[(size_t)col * DS_STRIDE + row + 8]       = acc[mt][nt][2];
                    Ds[(size_t)(col + 1) * DS_STRIDE + row + 8] = acc[mt][nt][3];
                }
            }
        }
        __syncthreads();
        #pragma unroll 4
        for (int i = 0; i < 16; i++) {
            int ocl = i * 8 + oq;
            int oc  = half * 128 + ocl;
            #pragma unroll
            for (int row2 = 0; row2 < 2; row2++) {
                float v = Ds[(size_t)ocl * DS_STRIDE + row2 * 64 + ow];
                int oh = oh0 + row2;
                if (valid)
                    outBase[(size_t)oc * (OHT * OWT) + (size_t)oh * OWT + ow] = v;
            }
        }
    }
}

extern "C" void kernel_launch(void* const* d_in, const int* in_sizes, int n_in,
                              void* d_out, int out_size)
{
    const float* in = (const float*)d_in[0];   // [32,128,64,64]
    const float* wt = (const float*)d_in[1];   // [256,128,3,3]
    float* out      = (float*)d_out;           // [32,256,62,62]

    cudaFuncSetAttribute(conv_mma_kernel,
                         cudaFuncAttributeMaxDynamicSharedMemorySize, SMEM_TOTAL);

    wcvt_kernel<<<(9 * OC * CIN + 255) / 256, 256>>>(wt);
    xcvt_kernel<<<dim3(2, 4, NB * HIN), dim3(32, 8)>>>(in);
    conv_mma_kernel<<<dim3(31, NB), 512, SMEM_TOTAL>>>(out);
}